// round 1
// baseline (speedup 1.0000x reference)
#include <cuda_runtime.h>

#define NN 50000
#define EE 600000
#define HH 128

// ---------------- scratch (static device arrays; no runtime allocation) ----
__device__ float g_h  [(size_t)NN * HH];   // node features (25.6 MB)
__device__ float g_agg[(size_t)NN * HH];   // aggregation buffer (25.6 MB)
__device__ float g_ea [(size_t)EE * HH];   // encoded edge features (307 MB)

typedef unsigned long long ull;

// ---------------- packed f32x2 helpers (sm_103a) ---------------------------
__device__ __forceinline__ ull pack2(float lo, float hi) {
    ull r; asm("mov.b64 %0, {%1,%2};" : "=l"(r) : "f"(lo), "f"(hi)); return r;
}
__device__ __forceinline__ float2 unpk(ull v) {
    float2 f; asm("mov.b64 {%0,%1}, %2;" : "=f"(f.x), "=f"(f.y) : "l"(v)); return f;
}
__device__ __forceinline__ void ffma2(ull& d, ull a, ull b) {
    asm("fma.rn.f32x2 %0, %1, %2, %0;" : "+l"(d) : "l"(a), "l"(b));
}
__device__ __forceinline__ float wsum(float v) {
#pragma unroll
    for (int o = 16; o > 0; o >>= 1) v += __shfl_xor_sync(0xffffffffu, v, o);
    return v;
}

// ============================================================================
// Encoder: out = LN( relu(in @ w1 + b1) @ w2 + b2 ), rows x (KIN -> 128 -> 128)
// Each warp: 8 rows, 32 lanes x 4 cols. Weights staged in SMEM once per block.
// ============================================================================
template <int KIN>
__global__ __launch_bounds__(256, 2)
void encoder_kernel(const float* __restrict__ in, int rows,
                    const float* __restrict__ w1, const float* __restrict__ b1,
                    const float* __restrict__ w2, const float* __restrict__ b2,
                    const float* __restrict__ gam, const float* __restrict__ bet,
                    float* __restrict__ out, float* __restrict__ out2)
{
    extern __shared__ float sm[];
    float* w1s  = sm;                    // KIN*128
    float* w2s  = sm + KIN * 128;        // 16384
    float* base = w2s + 16384;
    const int warp = threadIdx.x >> 5, lane = threadIdx.x & 31;
    float* in_s  = base + warp * (8 * KIN);
    float* hid_s = base + 8 * (8 * KIN) + warp * 1024;

    for (int i = threadIdx.x; i < KIN * 128; i += 256) w1s[i] = w1[i];
    for (int i = threadIdx.x; i < 16384;     i += 256) w2s[i] = w2[i];
    __syncthreads();

    const float4 b1v = ((const float4*)b1)[lane];
    const float4 b2v = ((const float4*)b2)[lane];
    const float4 gv  = ((const float4*)gam)[lane];
    const float4 bev = ((const float4*)bet)[lane];

    const int tiles = (rows + 7) >> 3;
    const int nw = gridDim.x * 8;
    for (int t = blockIdx.x * 8 + warp; t < tiles; t += nw) {
        const int r0 = t * 8;
        // stage inputs (8 rows x KIN)
        for (int i = lane; i < 8 * KIN; i += 32) {
            int rr = i / KIN; int idx = r0 + rr;
            in_s[i] = (idx < rows) ? in[(size_t)idx * KIN + (i - rr * KIN)] : 0.f;
        }
        __syncwarp();

        // ---- layer 1 ----
        ull a1[8][2];
#pragma unroll
        for (int r = 0; r < 8; r++) { a1[r][0] = 0ULL; a1[r][1] = 0ULL; }
#pragma unroll
        for (int k = 0; k < KIN; k++) {
            ulonglong2 w = ((const ulonglong2*)w1s)[k * 32 + lane];
#pragma unroll
            for (int r = 0; r < 8; r++) {
                float xv = in_s[r * KIN + k];
                ull xp = pack2(xv, xv);
                ffma2(a1[r][0], xp, w.x);
                ffma2(a1[r][1], xp, w.y);
            }
        }
#pragma unroll
        for (int r = 0; r < 8; r++) {
            float2 p = unpk(a1[r][0]), q = unpk(a1[r][1]);
            float4 hv;
            hv.x = fmaxf(p.x + b1v.x, 0.f);
            hv.y = fmaxf(p.y + b1v.y, 0.f);
            hv.z = fmaxf(q.x + b1v.z, 0.f);
            hv.w = fmaxf(q.y + b1v.w, 0.f);
            ((float4*)hid_s)[r * 32 + lane] = hv;
        }
        __syncwarp();

        // ---- layer 2 ----
        ull a2[8][2];
#pragma unroll
        for (int r = 0; r < 8; r++) { a2[r][0] = 0ULL; a2[r][1] = 0ULL; }
#pragma unroll 4
        for (int k = 0; k < 128; k++) {
            ulonglong2 w = ((const ulonglong2*)w2s)[k * 32 + lane];
#pragma unroll
            for (int r = 0; r < 8; r++) {
                float xv = hid_s[r * 128 + k];
                ull xp = pack2(xv, xv);
                ffma2(a2[r][0], xp, w.x);
                ffma2(a2[r][1], xp, w.y);
            }
        }
        // ---- bias + LayerNorm + store ----
#pragma unroll
        for (int r = 0; r < 8; r++) {
            int idx = r0 + r;
            float2 p = unpk(a2[r][0]), q = unpk(a2[r][1]);
            float v0 = p.x + b2v.x, v1 = p.y + b2v.y;
            float v2 = q.x + b2v.z, v3 = q.y + b2v.w;
            float mean = wsum(v0 + v1 + v2 + v3) * 0.0078125f;
            float d0 = v0 - mean, d1 = v1 - mean, d2 = v2 - mean, d3 = v3 - mean;
            float var = wsum(d0 * d0 + d1 * d1 + d2 * d2 + d3 * d3) * 0.0078125f;
            float inv = rsqrtf(var + 1e-5f);
            if (idx < rows) {
                float4 o;
                o.x = d0 * inv * gv.x + bev.x;
                o.y = d1 * inv * gv.y + bev.y;
                o.z = d2 * inv * gv.z + bev.z;
                o.w = d3 * inv * gv.w + bev.w;
                ((float4*)out)[(size_t)idx * 32 + lane] = o;
                if (out2) ((float4*)out2)[(size_t)idx * 32 + lane] = o;
            }
        }
        __syncwarp();
    }
}

// ============================================================================
// GINEConv MLP + residual + LN:
//   h_new = LN( h + relu( relu(agg@w1+b1)@w2 + b2 ) ); writes h and agg=h_new
// ============================================================================
__global__ __launch_bounds__(256, 1)
void conv_kernel(float* __restrict__ agg, float* __restrict__ h, int rows,
                 const float* __restrict__ w1, const float* __restrict__ b1,
                 const float* __restrict__ w2, const float* __restrict__ b2,
                 const float* __restrict__ gam, const float* __restrict__ bet)
{
    extern __shared__ float sm[];
    float* w1s = sm;            // 16384
    float* w2s = sm + 16384;    // 16384
    float* base = sm + 32768;
    const int warp = threadIdx.x >> 5, lane = threadIdx.x & 31;
    float* in_s  = base + warp * 1024;
    float* hid_s = base + 8192 + warp * 1024;

    for (int i = threadIdx.x; i < 16384; i += 256) { w1s[i] = w1[i]; w2s[i] = w2[i]; }
    __syncthreads();

    const float4 b1v = ((const float4*)b1)[lane];
    const float4 b2v = ((const float4*)b2)[lane];
    const float4 gv  = ((const float4*)gam)[lane];
    const float4 bev = ((const float4*)bet)[lane];

    const int tiles = (rows + 7) >> 3;
    const int nw = gridDim.x * 8;
    for (int t = blockIdx.x * 8 + warp; t < tiles; t += nw) {
        const int r0 = t * 8;
#pragma unroll
        for (int r = 0; r < 8; r++) {
            int idx = r0 + r;
            float4 v = (idx < rows) ? ((const float4*)agg)[(size_t)idx * 32 + lane]
                                    : make_float4(0.f, 0.f, 0.f, 0.f);
            ((float4*)in_s)[r * 32 + lane] = v;
        }
        __syncwarp();

        ull a1[8][2];
#pragma unroll
        for (int r = 0; r < 8; r++) { a1[r][0] = 0ULL; a1[r][1] = 0ULL; }
#pragma unroll 4
        for (int k = 0; k < 128; k++) {
            ulonglong2 w = ((const ulonglong2*)w1s)[k * 32 + lane];
#pragma unroll
            for (int r = 0; r < 8; r++) {
                float xv = in_s[r * 128 + k];
                ull xp = pack2(xv, xv);
                ffma2(a1[r][0], xp, w.x);
                ffma2(a1[r][1], xp, w.y);
            }
        }
#pragma unroll
        for (int r = 0; r < 8; r++) {
            float2 p = unpk(a1[r][0]), q = unpk(a1[r][1]);
            float4 hv;
            hv.x = fmaxf(p.x + b1v.x, 0.f);
            hv.y = fmaxf(p.y + b1v.y, 0.f);
            hv.z = fmaxf(q.x + b1v.z, 0.f);
            hv.w = fmaxf(q.y + b1v.w, 0.f);
            ((float4*)hid_s)[r * 32 + lane] = hv;
        }
        __syncwarp();

        ull a2[8][2];
#pragma unroll
        for (int r = 0; r < 8; r++) { a2[r][0] = 0ULL; a2[r][1] = 0ULL; }
#pragma unroll 4
        for (int k = 0; k < 128; k++) {
            ulonglong2 w = ((const ulonglong2*)w2s)[k * 32 + lane];
#pragma unroll
            for (int r = 0; r < 8; r++) {
                float xv = hid_s[r * 128 + k];
                ull xp = pack2(xv, xv);
                ffma2(a2[r][0], xp, w.x);
                ffma2(a2[r][1], xp, w.y);
            }
        }
#pragma unroll
        for (int r = 0; r < 8; r++) {
            int idx = r0 + r;
            float4 hold = (idx < rows) ? ((const float4*)h)[(size_t)idx * 32 + lane]
                                       : make_float4(0.f, 0.f, 0.f, 0.f);
            float2 p = unpk(a2[r][0]), q = unpk(a2[r][1]);
            float v0 = hold.x + fmaxf(p.x + b2v.x, 0.f);
            float v1 = hold.y + fmaxf(p.y + b2v.y, 0.f);
            float v2 = hold.z + fmaxf(q.x + b2v.z, 0.f);
            float v3 = hold.w + fmaxf(q.y + b2v.w, 0.f);
            float mean = wsum(v0 + v1 + v2 + v3) * 0.0078125f;
            float d0 = v0 - mean, d1 = v1 - mean, d2 = v2 - mean, d3 = v3 - mean;
            float var = wsum(d0 * d0 + d1 * d1 + d2 * d2 + d3 * d3) * 0.0078125f;
            float inv = rsqrtf(var + 1e-5f);
            if (idx < rows) {
                float4 o;
                o.x = d0 * inv * gv.x + bev.x;
                o.y = d1 * inv * gv.y + bev.y;
                o.z = d2 * inv * gv.z + bev.z;
                o.w = d3 * inv * gv.w + bev.w;
                ((float4*)h)[(size_t)idx * 32 + lane]   = o;
                ((float4*)agg)[(size_t)idx * 32 + lane] = o;  // init next layer's accumulator
            }
        }
        __syncwarp();
    }
}

// ============================================================================
// Message passing: agg[dst] += relu(h[src] + ea[e])   (agg pre-initialized = h)
// one thread per (edge, 4-float chunk)
// ============================================================================
__global__ void msg_kernel(const int* __restrict__ ei,
                           const float* __restrict__ h,
                           const float* __restrict__ ea,
                           float* __restrict__ agg)
{
    int idx = blockIdx.x * blockDim.x + threadIdx.x;
    if (idx >= EE * 32) return;
    int e = idx >> 5, c = idx & 31;
    int src = __ldg(&ei[e]);
    int dst = __ldg(&ei[EE + e]);
    float4 hv = __ldg((const float4*)h + (size_t)src * 32 + c);
    float4 ev = __ldg((const float4*)ea + (size_t)e * 32 + c);
    float m0 = fmaxf(hv.x + ev.x, 0.f);
    float m1 = fmaxf(hv.y + ev.y, 0.f);
    float m2 = fmaxf(hv.z + ev.z, 0.f);
    float m3 = fmaxf(hv.w + ev.w, 0.f);
    float* a = agg + (size_t)dst * 128 + c * 4;
    atomicAdd(a + 0, m0);
    atomicAdd(a + 1, m1);
    atomicAdd(a + 2, m2);
    atomicAdd(a + 3, m3);
}

// ============================================================================
// Heads: u = mlp(h,128->64->3)*disp ; log_s = clip(mlp(h,128->64->1),0,30)
//        s = exp(log_s) ; safety = YIELD/(s+1e-8). One warp per node.
// Output layout: u[3N] | s[N] | log_s[N] | disp_scale[1] | safety[N]
// ============================================================================
__global__ void heads_kernel(const float* __restrict__ h,
                             const float* __restrict__ dw1, const float* __restrict__ db1,
                             const float* __restrict__ dw2, const float* __restrict__ db2,
                             const float* __restrict__ sw1, const float* __restrict__ sb1,
                             const float* __restrict__ sw2, const float* __restrict__ sb2,
                             const float* __restrict__ lds,
                             float* __restrict__ out, int rows)
{
    __shared__ float hs[8][128];
    const int warp = threadIdx.x >> 5, lane = threadIdx.x & 31;
    const int node = blockIdx.x * 8 + warp;
    float disp = 0.001f + log1pf(expf(*lds));
    if (blockIdx.x == 0 && threadIdx.x == 0) out[5 * NN] = disp;
    if (node >= rows) return;

    float4 hv = ((const float4*)h)[(size_t)node * 32 + lane];
    ((float4*)hs[warp])[lane] = hv;
    __syncwarp();

    float d0 = db1[lane], d1 = db1[lane + 32];
    float s0 = sb1[lane], s1 = sb1[lane + 32];
#pragma unroll 4
    for (int k = 0; k < 128; k++) {
        float xv = hs[warp][k];
        d0 = fmaf(xv, __ldg(&dw1[k * 64 + lane]),      d0);
        d1 = fmaf(xv, __ldg(&dw1[k * 64 + lane + 32]), d1);
        s0 = fmaf(xv, __ldg(&sw1[k * 64 + lane]),      s0);
        s1 = fmaf(xv, __ldg(&sw1[k * 64 + lane + 32]), s1);
    }
    d0 = fmaxf(d0, 0.f); d1 = fmaxf(d1, 0.f);
    s0 = fmaxf(s0, 0.f); s1 = fmaxf(s1, 0.f);

    float p0 = d0 * dw2[lane * 3 + 0] + d1 * dw2[(lane + 32) * 3 + 0];
    float p1 = d0 * dw2[lane * 3 + 1] + d1 * dw2[(lane + 32) * 3 + 1];
    float p2 = d0 * dw2[lane * 3 + 2] + d1 * dw2[(lane + 32) * 3 + 2];
    float ps = s0 * sw2[lane] + s1 * sw2[lane + 32];
    p0 = wsum(p0); p1 = wsum(p1); p2 = wsum(p2); ps = wsum(ps);

    if (lane == 0) {
        float u0 = (p0 + db2[0]) * disp;
        float u1 = (p1 + db2[1]) * disp;
        float u2 = (p2 + db2[2]) * disp;
        float ls = ps + sb2[0];
        ls = fminf(fmaxf(ls, 0.f), 30.f);
        float s = expf(ls);
        float sf = 2.5e8f / (s + 1e-8f);
        out[node * 3 + 0] = u0;
        out[node * 3 + 1] = u1;
        out[node * 3 + 2] = u2;
        out[3 * NN + node] = s;
        out[4 * NN + node] = ls;
        out[5 * NN + 1 + node] = sf;
    }
}

// ============================================================================
extern "C" void kernel_launch(void* const* d_in, const int* in_sizes, int n_in,
                              void* d_out, int out_size)
{
    const float* x     = (const float*)d_in[0];
    const float* eattr = (const float*)d_in[1];
    const int*   ei    = (const int*)  d_in[2];
    const float* ne_w1 = (const float*)d_in[3];
    const float* ne_b1 = (const float*)d_in[4];
    const float* ne_w2 = (const float*)d_in[5];
    const float* ne_b2 = (const float*)d_in[6];
    const float* ne_g  = (const float*)d_in[7];
    const float* ne_be = (const float*)d_in[8];
    const float* ee_w1 = (const float*)d_in[9];
    const float* ee_b1 = (const float*)d_in[10];
    const float* ee_w2 = (const float*)d_in[11];
    const float* ee_b2 = (const float*)d_in[12];
    const float* ee_g  = (const float*)d_in[13];
    const float* ee_be = (const float*)d_in[14];
    const float* cw1   = (const float*)d_in[15];
    const float* cb1   = (const float*)d_in[16];
    const float* cw2   = (const float*)d_in[17];
    const float* cb2   = (const float*)d_in[18];
    const float* pn_g  = (const float*)d_in[19];
    const float* pn_be = (const float*)d_in[20];
    const float* dw1   = (const float*)d_in[21];
    const float* db1   = (const float*)d_in[22];
    const float* dw2   = (const float*)d_in[23];
    const float* db2   = (const float*)d_in[24];
    const float* sw1   = (const float*)d_in[25];
    const float* sb1   = (const float*)d_in[26];
    const float* sw2   = (const float*)d_in[27];
    const float* sb2   = (const float*)d_in[28];
    const float* ldsc  = (const float*)d_in[29];
    float* out = (float*)d_out;

    void *ph, *pa, *pe;
    cudaGetSymbolAddress(&ph, g_h);
    cudaGetSymbolAddress(&pa, g_agg);
    cudaGetSymbolAddress(&pe, g_ea);
    float* hbuf = (float*)ph;
    float* abuf = (float*)pa;
    float* ebuf = (float*)pe;

    const int enc5_smem = (5 * 128 + 16384 + 64 * 5 + 8192) * 4;
    const int enc6_smem = (6 * 128 + 16384 + 64 * 6 + 8192) * 4;
    const int conv_smem = 49152 * 4;
    cudaFuncSetAttribute(encoder_kernel<5>, cudaFuncAttributeMaxDynamicSharedMemorySize, enc5_smem);
    cudaFuncSetAttribute(encoder_kernel<6>, cudaFuncAttributeMaxDynamicSharedMemorySize, enc6_smem);
    cudaFuncSetAttribute(conv_kernel,       cudaFuncAttributeMaxDynamicSharedMemorySize, conv_smem);

    // node encoder: writes h and agg=h
    encoder_kernel<5><<<296, 256, enc5_smem>>>(x, NN, ne_w1, ne_b1, ne_w2, ne_b2,
                                               ne_g, ne_be, hbuf, abuf);
    // edge encoder: writes ea
    encoder_kernel<6><<<296, 256, enc6_smem>>>(eattr, EE, ee_w1, ee_b1, ee_w2, ee_b2,
                                               ee_g, ee_be, ebuf, nullptr);
    for (int l = 0; l < 3; l++) {
        msg_kernel<<<(EE * 32 + 255) / 256, 256>>>(ei, hbuf, ebuf, abuf);
        conv_kernel<<<148, 256, conv_smem>>>(abuf, hbuf, NN,
                                             cw1 + (size_t)l * 16384, cb1 + l * 128,
                                             cw2 + (size_t)l * 16384, cb2 + l * 128,
                                             pn_g + l * 128, pn_be + l * 128);
    }
    heads_kernel<<<(NN + 7) / 8, 256>>>(hbuf, dw1, db1, dw2, db2,
                                        sw1, sb1, sw2, sb2, ldsc, out, NN);
}

// round 3
// speedup vs baseline: 1.0120x; 1.0120x over previous
#include <cuda_runtime.h>
#include <cstdint>

#define NN 50000
#define EE 600000

// ---------------- scratch ---------------------------------------------------
__device__ float g_h  [(size_t)NN * 128];
__device__ float g_agg[(size_t)NN * 128];
__device__ float g_t  [(size_t)NN * 128];
__device__ float g_ea [(size_t)EE * 128];

// ---------------- helpers ----------------------------------------------------
__device__ __forceinline__ uint32_t tf32u(float v) {
    uint32_t r; asm("cvt.rna.tf32.f32 %0, %1;" : "=r"(r) : "f"(v)); return r;
}
__device__ __forceinline__ void mma_tf32(float* d,
                                         uint32_t a0, uint32_t a1, uint32_t a2, uint32_t a3,
                                         uint32_t b0, uint32_t b1) {
    asm volatile("mma.sync.aligned.m16n8k8.row.col.f32.tf32.tf32.f32 "
        "{%0,%1,%2,%3}, {%4,%5,%6,%7}, {%8,%9}, {%0,%1,%2,%3};"
        : "+f"(d[0]), "+f"(d[1]), "+f"(d[2]), "+f"(d[3])
        : "r"(a0), "r"(a1), "r"(a2), "r"(a3), "r"(b0), "r"(b1));
}
__device__ __forceinline__ float wsum(float v) {
#pragma unroll
    for (int o = 16; o > 0; o >>= 1) v += __shfl_xor_sync(0xffffffffu, v, o);
    return v;
}

// SMEM strides (floats) — padded for conflict-free fragment access
#define SA 132   // A rows: bank = (4*row + k) % 32, distinct over g,t4
#define SB 136   // B rows: bank = (8*k + n) % 32, distinct over t4,g

// ============================================================================
// Fused GEMM (out = f(A[rows,128] @ W[128,128])) via mma.sync 3xTF32.
// Persistent CTAs; 128x128 tile per CTA; warp tile 32x64.
// MODE 0: A = relu(x[KIN] @ w1 + b1) computed SIMT; epi: LN(D + b) -> out1 (+out2)
// MODE 1: A from gmem;                              epi: relu(D + b) -> out1
// MODE 2: A from gmem;                              epi: LN(hres + relu(D + b)) -> out1, out2
// ============================================================================
template <int KIN, int MODE>
__global__ __launch_bounds__(256, 1)
void gemm128_kernel(const float* __restrict__ A, int rows,
                    const float* __restrict__ W, const float* __restrict__ bias,
                    const float* __restrict__ w1, const float* __restrict__ b1,
                    const float* __restrict__ gam, const float* __restrict__ bet,
                    const float* __restrict__ hres,
                    float* __restrict__ out1, float* __restrict__ out2)
{
    extern __shared__ float dyn[];
    float*    As  = dyn;                    // [128][SA] fp32 (also reused for D)
    uint32_t* Bhi = (uint32_t*)(dyn + 128 * SA);          // [128][SB] tf32 bits
    uint32_t* Blo = (uint32_t*)(dyn + 128 * SA + 128 * SB);
    __shared__ float w1s[KIN > 0 ? KIN * 128 : 1];
    __shared__ float b1s[128], bs[128], gs[128], bes[128];

    const int tid  = threadIdx.x;
    const int lane = tid & 31;
    const int wrp  = tid >> 5;
    const int wm   = (wrp & 3) * 32;   // warp row offset in tile
    const int wn   = (wrp >> 2) * 64;  // warp col offset in tile
    const int g    = lane >> 2;        // groupID
    const int t4   = lane & 3;         // threadID_in_group

    // ---- stage B = W (k-major [128][128]) as tf32 hi/lo --------------------
    for (int i = tid; i < 16384; i += 256) {
        int k = i >> 7, n = i & 127;
        float v = W[i];
        uint32_t hi = tf32u(v);
        Bhi[k * SB + n] = hi;
        Blo[k * SB + n] = tf32u(v - __uint_as_float(hi));
    }
    if (KIN > 0) {
        for (int i = tid; i < KIN * 128; i += 256) w1s[i] = w1[i];
        if (tid < 128) b1s[tid] = b1[tid];
    }
    if (tid < 128) {
        bs[tid] = bias[tid];
        if (MODE != 1) { gs[tid] = gam[tid]; bes[tid] = bet[tid]; }
    }
    __syncthreads();

    const int ntiles = (rows + 127) >> 7;
    for (int t = blockIdx.x; t < ntiles; t += gridDim.x) {
        const int row0 = t << 7;

        // ---------------- stage A tile into SMEM (fp32) ----------------
        if (KIN > 0) {
            // layer-1 SIMT: thread handles row (tid&127), cols half*64..+64
            const int r = tid & 127, half = tid >> 7, rw = row0 + r;
            float xr[KIN > 0 ? KIN : 1];
#pragma unroll
            for (int j = 0; j < KIN; j++)
                xr[j] = (rw < rows) ? A[(size_t)rw * KIN + j] : 0.f;
#pragma unroll 8
            for (int c = half * 64; c < half * 64 + 64; c++) {
                float acc = b1s[c];
#pragma unroll
                for (int j = 0; j < KIN; j++) acc = fmaf(xr[j], w1s[j * 128 + c], acc);
                As[r * SA + c] = fmaxf(acc, 0.f);
            }
        } else {
#pragma unroll
            for (int q = 0; q < 16; q++) {
                int i = q * 256 + tid;
                int r = i >> 5, c4 = (i & 31) << 2;
                float4 v = (row0 + r < rows)
                    ? __ldg((const float4*)(A + (size_t)(row0 + r) * 128 + c4))
                    : make_float4(0.f, 0.f, 0.f, 0.f);
                *(float4*)(As + r * SA + c4) = v;
            }
        }
        __syncthreads();

        // ---------------- mainloop: 16 k-steps, 3xTF32 ----------------
        float d[2][8][4];
#pragma unroll
        for (int mt = 0; mt < 2; mt++)
#pragma unroll
            for (int nt = 0; nt < 8; nt++)
#pragma unroll
                for (int i = 0; i < 4; i++) d[mt][nt][i] = 0.f;

#pragma unroll 1
        for (int ks = 0; ks < 16; ks++) {
            const int k0 = ks * 8;
            uint32_t ahi[2][4], alo[2][4];
#pragma unroll
            for (int mt = 0; mt < 2; mt++) {
                const int rb = wm + mt * 16 + g;
                float r0 = As[rb * SA + k0 + t4];
                float r1 = As[(rb + 8) * SA + k0 + t4];
                float r2 = As[rb * SA + k0 + t4 + 4];
                float r3 = As[(rb + 8) * SA + k0 + t4 + 4];
                ahi[mt][0] = tf32u(r0); alo[mt][0] = tf32u(r0 - __uint_as_float(ahi[mt][0]));
                ahi[mt][1] = tf32u(r1); alo[mt][1] = tf32u(r1 - __uint_as_float(ahi[mt][1]));
                ahi[mt][2] = tf32u(r2); alo[mt][2] = tf32u(r2 - __uint_as_float(ahi[mt][2]));
                ahi[mt][3] = tf32u(r3); alo[mt][3] = tf32u(r3 - __uint_as_float(ahi[mt][3]));
            }
#pragma unroll
            for (int nt = 0; nt < 8; nt++) {
                const int n0 = wn + nt * 8 + g;
                uint32_t bh0 = Bhi[(k0 + t4) * SB + n0];
                uint32_t bh1 = Bhi[(k0 + t4 + 4) * SB + n0];
                uint32_t bl0 = Blo[(k0 + t4) * SB + n0];
                uint32_t bl1 = Blo[(k0 + t4 + 4) * SB + n0];
#pragma unroll
                for (int mt = 0; mt < 2; mt++) {
                    mma_tf32(d[mt][nt], ahi[mt][0], ahi[mt][1], ahi[mt][2], ahi[mt][3], bh0, bh1);
                    mma_tf32(d[mt][nt], alo[mt][0], alo[mt][1], alo[mt][2], alo[mt][3], bh0, bh1);
                    mma_tf32(d[mt][nt], ahi[mt][0], ahi[mt][1], ahi[mt][2], ahi[mt][3], bl0, bl1);
                }
            }
        }
        __syncthreads();

        // ---------------- write D fragments back into As ----------------
#pragma unroll
        for (int mt = 0; mt < 2; mt++) {
            const int rb = wm + mt * 16 + g;
#pragma unroll
            for (int nt = 0; nt < 8; nt++) {
                const int cb = wn + nt * 8 + 2 * t4;
                *(float2*)(As + rb * SA + cb)       = make_float2(d[mt][nt][0], d[mt][nt][1]);
                *(float2*)(As + (rb + 8) * SA + cb) = make_float2(d[mt][nt][2], d[mt][nt][3]);
            }
        }
        __syncthreads();

        // ---------------- epilogue: row per thread ----------------
        if (tid < 128) {
            const int rw = row0 + tid;
            const bool valid = rw < rows;
            float dv[128];
            if (MODE == 1) {
                if (valid) {
#pragma unroll
                    for (int q = 0; q < 32; q++) {
                        float4 v = *(const float4*)(As + tid * SA + q * 4);
                        float4 o;
                        o.x = fmaxf(v.x + bs[q * 4 + 0], 0.f);
                        o.y = fmaxf(v.y + bs[q * 4 + 1], 0.f);
                        o.z = fmaxf(v.z + bs[q * 4 + 2], 0.f);
                        o.w = fmaxf(v.w + bs[q * 4 + 3], 0.f);
                        ((float4*)(out1 + (size_t)rw * 128))[q] = o;
                    }
                }
            } else {
#pragma unroll
                for (int q = 0; q < 32; q++) {
                    float4 v = *(const float4*)(As + tid * SA + q * 4);
                    if (MODE == 2) {
                        float4 hv = valid ? ((const float4*)(hres + (size_t)rw * 128))[q]
                                          : make_float4(0.f, 0.f, 0.f, 0.f);
                        dv[q * 4 + 0] = hv.x + fmaxf(v.x + bs[q * 4 + 0], 0.f);
                        dv[q * 4 + 1] = hv.y + fmaxf(v.y + bs[q * 4 + 1], 0.f);
                        dv[q * 4 + 2] = hv.z + fmaxf(v.z + bs[q * 4 + 2], 0.f);
                        dv[q * 4 + 3] = hv.w + fmaxf(v.w + bs[q * 4 + 3], 0.f);
                    } else {
                        dv[q * 4 + 0] = v.x + bs[q * 4 + 0];
                        dv[q * 4 + 1] = v.y + bs[q * 4 + 1];
                        dv[q * 4 + 2] = v.z + bs[q * 4 + 2];
                        dv[q * 4 + 3] = v.w + bs[q * 4 + 3];
                    }
                }
                float sum = 0.f;
#pragma unroll
                for (int i = 0; i < 128; i++) sum += dv[i];
                float mean = sum * 0.0078125f;
                float var = 0.f;
#pragma unroll
                for (int i = 0; i < 128; i++) { float e = dv[i] - mean; var += e * e; }
                float inv = rsqrtf(var * 0.0078125f + 1e-5f);
                if (valid) {
#pragma unroll
                    for (int q = 0; q < 32; q++) {
                        float4 o;
                        o.x = (dv[q * 4 + 0] - mean) * inv * gs[q * 4 + 0] + bes[q * 4 + 0];
                        o.y = (dv[q * 4 + 1] - mean) * inv * gs[q * 4 + 1] + bes[q * 4 + 1];
                        o.z = (dv[q * 4 + 2] - mean) * inv * gs[q * 4 + 2] + bes[q * 4 + 2];
                        o.w = (dv[q * 4 + 3] - mean) * inv * gs[q * 4 + 3] + bes[q * 4 + 3];
                        ((float4*)(out1 + (size_t)rw * 128))[q] = o;
                        if (out2) ((float4*)(out2 + (size_t)rw * 128))[q] = o;
                    }
                }
            }
        }
        __syncthreads();  // As reused next tile
    }
}

// ============================================================================
// Message passing: agg[dst] += relu(h[src] + ea[e])   (agg pre-initialized = h)
// ============================================================================
__global__ void msg_kernel(const int* __restrict__ ei,
                           const float* __restrict__ h,
                           const float* __restrict__ ea,
                           float* __restrict__ agg)
{
    int idx = blockIdx.x * blockDim.x + threadIdx.x;
    if (idx >= EE * 32) return;
    int e = idx >> 5, c = idx & 31;
    int src = __ldg(&ei[e]);
    int dst = __ldg(&ei[EE + e]);
    float4 hv = __ldg((const float4*)h + (size_t)src * 32 + c);
    float4 ev = __ldg((const float4*)ea + (size_t)e * 32 + c);
    float* a = agg + (size_t)dst * 128 + c * 4;
    atomicAdd(a + 0, fmaxf(hv.x + ev.x, 0.f));
    atomicAdd(a + 1, fmaxf(hv.y + ev.y, 0.f));
    atomicAdd(a + 2, fmaxf(hv.z + ev.z, 0.f));
    atomicAdd(a + 3, fmaxf(hv.w + ev.w, 0.f));
}

// ============================================================================
// Heads: one warp per node. Output: u[3N] | s[N] | log_s[N] | disp[1] | safety[N]
// ============================================================================
__global__ void heads_kernel(const float* __restrict__ h,
                             const float* __restrict__ dw1, const float* __restrict__ db1,
                             const float* __restrict__ dw2, const float* __restrict__ db2,
                             const float* __restrict__ sw1, const float* __restrict__ sb1,
                             const float* __restrict__ sw2, const float* __restrict__ sb2,
                             const float* __restrict__ lds,
                             float* __restrict__ out, int rows)
{
    __shared__ float hs[8][128];
    const int warp = threadIdx.x >> 5, lane = threadIdx.x & 31;
    const int node = blockIdx.x * 8 + warp;
    float disp = 0.001f + log1pf(expf(*lds));
    if (blockIdx.x == 0 && threadIdx.x == 0) out[5 * NN] = disp;
    if (node >= rows) return;

    float4 hv = ((const float4*)h)[(size_t)node * 32 + lane];
    ((float4*)hs[warp])[lane] = hv;
    __syncwarp();

    float d0 = db1[lane], d1 = db1[lane + 32];
    float s0 = sb1[lane], s1 = sb1[lane + 32];
#pragma unroll 4
    for (int k = 0; k < 128; k++) {
        float xv = hs[warp][k];
        d0 = fmaf(xv, __ldg(&dw1[k * 64 + lane]),      d0);
        d1 = fmaf(xv, __ldg(&dw1[k * 64 + lane + 32]), d1);
        s0 = fmaf(xv, __ldg(&sw1[k * 64 + lane]),      s0);
        s1 = fmaf(xv, __ldg(&sw1[k * 64 + lane + 32]), s1);
    }
    d0 = fmaxf(d0, 0.f); d1 = fmaxf(d1, 0.f);
    s0 = fmaxf(s0, 0.f); s1 = fmaxf(s1, 0.f);

    float p0 = d0 * dw2[lane * 3 + 0] + d1 * dw2[(lane + 32) * 3 + 0];
    float p1 = d0 * dw2[lane * 3 + 1] + d1 * dw2[(lane + 32) * 3 + 1];
    float p2 = d0 * dw2[lane * 3 + 2] + d1 * dw2[(lane + 32) * 3 + 2];
    float ps = s0 * sw2[lane] + s1 * sw2[lane + 32];
    p0 = wsum(p0); p1 = wsum(p1); p2 = wsum(p2); ps = wsum(ps);

    if (lane == 0) {
        float ls = ps + sb2[0];
        ls = fminf(fmaxf(ls, 0.f), 30.f);
        float s = expf(ls);
        out[node * 3 + 0] = (p0 + db2[0]) * disp;
        out[node * 3 + 1] = (p1 + db2[1]) * disp;
        out[node * 3 + 2] = (p2 + db2[2]) * disp;
        out[3 * NN + node] = s;
        out[4 * NN + node] = ls;
        out[5 * NN + 1 + node] = 2.5e8f / (s + 1e-8f);
    }
}

// ============================================================================
extern "C" void kernel_launch(void* const* d_in, const int* in_sizes, int n_in,
                              void* d_out, int out_size)
{
    const float* x     = (const float*)d_in[0];
    const float* eattr = (const float*)d_in[1];
    const int*   ei    = (const int*)  d_in[2];
    const float* ne_w1 = (const float*)d_in[3];
    const float* ne_b1 = (const float*)d_in[4];
    const float* ne_w2 = (const float*)d_in[5];
    const float* ne_b2 = (const float*)d_in[6];
    const float* ne_g  = (const float*)d_in[7];
    const float* ne_be = (const float*)d_in[8];
    const float* ee_w1 = (const float*)d_in[9];
    const float* ee_b1 = (const float*)d_in[10];
    const float* ee_w2 = (const float*)d_in[11];
    const float* ee_b2 = (const float*)d_in[12];
    const float* ee_g  = (const float*)d_in[13];
    const float* ee_be = (const float*)d_in[14];
    const float* cw1   = (const float*)d_in[15];
    const float* cb1   = (const float*)d_in[16];
    const float* cw2   = (const float*)d_in[17];
    const float* cb2   = (const float*)d_in[18];
    const float* pn_g  = (const float*)d_in[19];
    const float* pn_be = (const float*)d_in[20];
    const float* dw1   = (const float*)d_in[21];
    const float* db1   = (const float*)d_in[22];
    const float* dw2   = (const float*)d_in[23];
    const float* db2   = (const float*)d_in[24];
    const float* sw1   = (const float*)d_in[25];
    const float* sb1   = (const float*)d_in[26];
    const float* sw2   = (const float*)d_in[27];
    const float* sb2   = (const float*)d_in[28];
    const float* ldsc  = (const float*)d_in[29];
    float* out = (float*)d_out;

    void *ph, *pa, *pt, *pe;
    cudaGetSymbolAddress(&ph, g_h);
    cudaGetSymbolAddress(&pa, g_agg);
    cudaGetSymbolAddress(&pt, g_t);
    cudaGetSymbolAddress(&pe, g_ea);
    float* hbuf = (float*)ph;
    float* abuf = (float*)pa;
    float* tbuf = (float*)pt;
    float* ebuf = (float*)pe;

    const int gsm = (128 * SA + 2 * 128 * SB) * 4;  // ~206 KB
    cudaFuncSetAttribute(gemm128_kernel<5, 0>, cudaFuncAttributeMaxDynamicSharedMemorySize, gsm);
    cudaFuncSetAttribute(gemm128_kernel<6, 0>, cudaFuncAttributeMaxDynamicSharedMemorySize, gsm);
    cudaFuncSetAttribute(gemm128_kernel<0, 1>, cudaFuncAttributeMaxDynamicSharedMemorySize, gsm);
    cudaFuncSetAttribute(gemm128_kernel<0, 2>, cudaFuncAttributeMaxDynamicSharedMemorySize, gsm);

    // node encoder: h = LN(mlp2(x)), agg = h
    gemm128_kernel<5, 0><<<148, 256, gsm>>>(x, NN, ne_w2, ne_b2, ne_w1, ne_b1,
                                            ne_g, ne_be, nullptr, hbuf, abuf);
    // edge encoder: ea = LN(mlp2(edge_attr))
    gemm128_kernel<6, 0><<<148, 256, gsm>>>(eattr, EE, ee_w2, ee_b2, ee_w1, ee_b1,
                                            ee_g, ee_be, nullptr, ebuf, nullptr);
    for (int l = 0; l < 3; l++) {
        msg_kernel<<<(EE * 32 + 255) / 256, 256>>>(ei, hbuf, ebuf, abuf);
        // t = relu(agg @ w1 + b1)
        gemm128_kernel<0, 1><<<148, 256, gsm>>>(abuf, NN, cw1 + (size_t)l * 16384, cb1 + l * 128,
                                                nullptr, nullptr, nullptr, nullptr, nullptr,
                                                tbuf, nullptr);
        // h = LN(h + relu(t @ w2 + b2)); agg = h
        gemm128_kernel<0, 2><<<148, 256, gsm>>>(tbuf, NN, cw2 + (size_t)l * 16384, cb2 + l * 128,
                                                nullptr, nullptr, pn_g + l * 128, pn_be + l * 128,
                                                hbuf, hbuf, abuf);
    }
    heads_kernel<<<(NN + 7) / 8, 256>>>(hbuf, dw1, db1, dw2, db2,
                                        sw1, sb1, sw2, sb2, ldsc, out, NN);
}

// round 4
// speedup vs baseline: 1.2463x; 1.2315x over previous
#include <cuda_runtime.h>
#include <cstdint>

#define NN 50000
#define EE 600000

// ---------------- scratch ---------------------------------------------------
__device__ float g_h  [(size_t)NN * 128];
__device__ float g_agg[(size_t)NN * 128];
__device__ float g_t  [(size_t)NN * 128];
__device__ float g_ea [(size_t)EE * 128];

// ---------------- helpers ----------------------------------------------------
// split (x0,x1) into packed bf16x2 hi and lo words: x ~= hi + lo, err ~2^-17
__device__ __forceinline__ void split2(float x0, float x1, uint32_t& hi, uint32_t& lo) {
    asm("cvt.rn.bf16x2.f32 %0, %2, %1;" : "=r"(hi) : "f"(x0), "f"(x1));  // lo half=x0, hi half=x1
    float h0 = __uint_as_float(hi << 16);
    float h1 = __uint_as_float(hi & 0xffff0000u);
    float l0 = x0 - h0, l1 = x1 - h1;
    asm("cvt.rn.bf16x2.f32 %0, %2, %1;" : "=r"(lo) : "f"(l0), "f"(l1));
}
__device__ __forceinline__ void mma_bf16(float* d,
                                         uint32_t a0, uint32_t a1, uint32_t a2, uint32_t a3,
                                         uint32_t b0, uint32_t b1) {
    asm volatile("mma.sync.aligned.m16n8k16.row.col.f32.bf16.bf16.f32 "
        "{%0,%1,%2,%3}, {%4,%5,%6,%7}, {%8,%9}, {%0,%1,%2,%3};"
        : "+f"(d[0]), "+f"(d[1]), "+f"(d[2]), "+f"(d[3])
        : "r"(a0), "r"(a1), "r"(a2), "r"(a3), "r"(b0), "r"(b1));
}
__device__ __forceinline__ float wsum(float v) {
#pragma unroll
    for (int o = 16; o > 0; o >>= 1) v += __shfl_xor_sync(0xffffffffu, v, o);
    return v;
}

// SMEM word strides
#define KS2 68     // packed-k2 row stride (64 words + 4 pad): bank = 4*row + k2 -> conflict-free
#define SD  132    // D epilogue stride

// word offsets inside dynamic smem (uint32 units)
#define OFF_AHI 0
#define OFF_ALO (128 * KS2)
#define OFF_BHI (2 * 128 * KS2)
#define OFF_BLO (3 * 128 * KS2)
#define SMEM_WORDS (4 * 128 * KS2)

// ============================================================================
// Fused GEMM (out = f(A[rows,128] @ W[128,128])) via mma.sync bf16-split.
// Persistent CTAs; 128x128 tile per CTA; 16 warps; warp tile 32x32.
// MODE 0: A = relu(x[KIN] @ w1 + b1) computed SIMT; epi: LN(D + b) -> out1 (+out2)
// MODE 1: A from gmem;                              epi: relu(D + b) -> out1
// MODE 2: A from gmem;                              epi: LN(hres + relu(D + b)) -> out1, out2
// ============================================================================
template <int KIN, int MODE>
__global__ __launch_bounds__(512, 1)
void gemm128_kernel(const float* __restrict__ A, int rows,
                    const float* __restrict__ W, const float* __restrict__ bias,
                    const float* __restrict__ w1, const float* __restrict__ b1,
                    const float* __restrict__ gam, const float* __restrict__ bet,
                    const float* __restrict__ hres,
                    float* __restrict__ out1, float* __restrict__ out2)
{
    extern __shared__ uint32_t dyn[];
    uint32_t* Ahi = dyn + OFF_AHI;
    uint32_t* Alo = dyn + OFF_ALO;
    uint32_t* Bhi = dyn + OFF_BHI;
    uint32_t* Blo = dyn + OFF_BLO;
    float*    Ds  = (float*)dyn;      // reused after mainloop: [128][SD]
    __shared__ float w1s[KIN > 0 ? KIN * 128 : 1];
    __shared__ float b1s[128], bs[128], gs[128], bes[128];

    const int tid  = threadIdx.x;
    const int lane = tid & 31;
    const int wrp  = tid >> 5;
    const int wm   = (wrp & 3) * 32;   // warp row offset
    const int wn   = (wrp >> 2) * 32;  // warp col offset
    const int g    = lane >> 2;        // groupID
    const int t4   = lane & 3;         // threadID_in_group

    // ---- stage B = W (K-major) as packed bf16x2 hi/lo: Bs[n][k2] ----------
#pragma unroll
    for (int q = 0; q < 16; q++) {
        int i  = q * 512 + tid;
        int n  = i & 127, k2 = i >> 7;
        float v0 = W[(2 * k2) * 128 + n];
        float v1 = W[(2 * k2 + 1) * 128 + n];
        uint32_t h, l; split2(v0, v1, h, l);
        Bhi[n * KS2 + k2] = h;
        Blo[n * KS2 + k2] = l;
    }
    if (KIN > 0) {
        for (int i = tid; i < KIN * 128; i += 512) w1s[i] = w1[i];
        if (tid < 128) b1s[tid] = b1[tid];
    }
    if (tid < 128) {
        bs[tid] = bias[tid];
        if (MODE != 1) { gs[tid] = gam[tid]; bes[tid] = bet[tid]; }
    }
    __syncthreads();

    const int ntiles = (rows + 127) >> 7;
    for (int t = blockIdx.x; t < ntiles; t += gridDim.x) {
        const int row0 = t << 7;

        // ---------------- stage A tile (packed bf16x2 hi/lo) ----------------
        if (KIN > 0) {
            // layer-1 SIMT: row = tid>>2, 32 cols per thread (piece = tid&3)
            const int r = tid >> 2, p = tid & 3, rw = row0 + r;
            float xr[KIN > 0 ? KIN : 1];
#pragma unroll
            for (int j = 0; j < KIN; j++)
                xr[j] = (rw < rows) ? A[(size_t)rw * KIN + j] : 0.f;
#pragma unroll
            for (int j = 0; j < 16; j++) {
                int c = p * 32 + 2 * j;
                float a0 = b1s[c], a1 = b1s[c + 1];
#pragma unroll
                for (int k = 0; k < KIN; k++) {
                    a0 = fmaf(xr[k], w1s[k * 128 + c], a0);
                    a1 = fmaf(xr[k], w1s[k * 128 + c + 1], a1);
                }
                a0 = fmaxf(a0, 0.f); a1 = fmaxf(a1, 0.f);
                uint32_t h, l; split2(a0, a1, h, l);
                Ahi[r * KS2 + p * 16 + j] = h;
                Alo[r * KS2 + p * 16 + j] = l;
            }
        } else {
#pragma unroll
            for (int q = 0; q < 16; q++) {
                int i  = q * 512 + tid;
                int r  = i >> 6, k2 = i & 63;
                float2 v = (row0 + r < rows)
                    ? *(const float2*)(A + (size_t)(row0 + r) * 128 + 2 * k2)
                    : make_float2(0.f, 0.f);
                uint32_t h, l; split2(v.x, v.y, h, l);
                Ahi[r * KS2 + k2] = h;
                Alo[r * KS2 + k2] = l;
            }
        }
        __syncthreads();

        // ---------------- mainloop: 8 k-steps (k=16 each), 3 bf16 terms ----
        float d[2][4][4];
#pragma unroll
        for (int mt = 0; mt < 2; mt++)
#pragma unroll
            for (int nt = 0; nt < 4; nt++)
#pragma unroll
                for (int i = 0; i < 4; i++) d[mt][nt][i] = 0.f;

#pragma unroll 1
        for (int ks = 0; ks < 8; ks++) {
            const int kb = ks * 8 + t4;
            uint32_t ah[2][4], al[2][4];
#pragma unroll
            for (int mt = 0; mt < 2; mt++) {
                const int rb = (wm + mt * 16 + g) * KS2 + kb;
                ah[mt][0] = Ahi[rb];
                ah[mt][1] = Ahi[rb + 8 * KS2];
                ah[mt][2] = Ahi[rb + 4];
                ah[mt][3] = Ahi[rb + 8 * KS2 + 4];
                al[mt][0] = Alo[rb];
                al[mt][1] = Alo[rb + 8 * KS2];
                al[mt][2] = Alo[rb + 4];
                al[mt][3] = Alo[rb + 8 * KS2 + 4];
            }
#pragma unroll
            for (int nt = 0; nt < 4; nt++) {
                const int nb = (wn + nt * 8 + g) * KS2 + kb;
                uint32_t bh0 = Bhi[nb], bh1 = Bhi[nb + 4];
                uint32_t bl0 = Blo[nb], bl1 = Blo[nb + 4];
#pragma unroll
                for (int mt = 0; mt < 2; mt++) {
                    mma_bf16(d[mt][nt], ah[mt][0], ah[mt][1], ah[mt][2], ah[mt][3], bh0, bh1);
                    mma_bf16(d[mt][nt], al[mt][0], al[mt][1], al[mt][2], al[mt][3], bh0, bh1);
                    mma_bf16(d[mt][nt], ah[mt][0], ah[mt][1], ah[mt][2], ah[mt][3], bl0, bl1);
                }
            }
        }
        __syncthreads();   // done reading A region; reuse as D

        // ---------------- write D fragments into smem ----------------
#pragma unroll
        for (int mt = 0; mt < 2; mt++) {
            const int rb = wm + mt * 16 + g;
#pragma unroll
            for (int nt = 0; nt < 4; nt++) {
                const int cb = wn + nt * 8 + 2 * t4;
                *(float2*)(Ds + rb * SD + cb)       = make_float2(d[mt][nt][0], d[mt][nt][1]);
                *(float2*)(Ds + (rb + 8) * SD + cb) = make_float2(d[mt][nt][2], d[mt][nt][3]);
            }
        }
        __syncthreads();

        // ---------------- epilogue: row per thread (tid < 128) ----------------
        if (tid < 128) {
            const int rw = row0 + tid;
            const bool valid = rw < rows;
            if (MODE == 1) {
                if (valid) {
#pragma unroll
                    for (int q = 0; q < 32; q++) {
                        float4 v = *(const float4*)(Ds + tid * SD + q * 4);
                        float4 o;
                        o.x = fmaxf(v.x + bs[q * 4 + 0], 0.f);
                        o.y = fmaxf(v.y + bs[q * 4 + 1], 0.f);
                        o.z = fmaxf(v.z + bs[q * 4 + 2], 0.f);
                        o.w = fmaxf(v.w + bs[q * 4 + 3], 0.f);
                        ((float4*)(out1 + (size_t)rw * 128))[q] = o;
                    }
                }
            } else {
                float dv[128];
#pragma unroll
                for (int q = 0; q < 32; q++) {
                    float4 v = *(const float4*)(Ds + tid * SD + q * 4);
                    if (MODE == 2) {
                        float4 hv = valid ? ((const float4*)(hres + (size_t)rw * 128))[q]
                                          : make_float4(0.f, 0.f, 0.f, 0.f);
                        dv[q * 4 + 0] = hv.x + fmaxf(v.x + bs[q * 4 + 0], 0.f);
                        dv[q * 4 + 1] = hv.y + fmaxf(v.y + bs[q * 4 + 1], 0.f);
                        dv[q * 4 + 2] = hv.z + fmaxf(v.z + bs[q * 4 + 2], 0.f);
                        dv[q * 4 + 3] = hv.w + fmaxf(v.w + bs[q * 4 + 3], 0.f);
                    } else {
                        dv[q * 4 + 0] = v.x + bs[q * 4 + 0];
                        dv[q * 4 + 1] = v.y + bs[q * 4 + 1];
                        dv[q * 4 + 2] = v.z + bs[q * 4 + 2];
                        dv[q * 4 + 3] = v.w + bs[q * 4 + 3];
                    }
                }
                float sum = 0.f;
#pragma unroll
                for (int i = 0; i < 128; i++) sum += dv[i];
                float mean = sum * 0.0078125f;
                float var = 0.f;
#pragma unroll
                for (int i = 0; i < 128; i++) { float e = dv[i] - mean; var += e * e; }
                float inv = rsqrtf(var * 0.0078125f + 1e-5f);
                if (valid) {
#pragma unroll
                    for (int q = 0; q < 32; q++) {
                        float4 o;
                        o.x = (dv[q * 4 + 0] - mean) * inv * gs[q * 4 + 0] + bes[q * 4 + 0];
                        o.y = (dv[q * 4 + 1] - mean) * inv * gs[q * 4 + 1] + bes[q * 4 + 1];
                        o.z = (dv[q * 4 + 2] - mean) * inv * gs[q * 4 + 2] + bes[q * 4 + 2];
                        o.w = (dv[q * 4 + 3] - mean) * inv * gs[q * 4 + 3] + bes[q * 4 + 3];
                        ((float4*)(out1 + (size_t)rw * 128))[q] = o;
                        if (out2) ((float4*)(out2 + (size_t)rw * 128))[q] = o;
                    }
                }
            }
        }
        __syncthreads();  // smem reused next tile
    }
}

// ============================================================================
// Message passing: agg[dst] += relu(h[src] + ea[e])   (agg pre-initialized = h)
// vectorized red.global.add.v4.f32 (sm_90+ baseline PTX)
// ============================================================================
__global__ void msg_kernel(const int* __restrict__ ei,
                           const float* __restrict__ h,
                           const float* __restrict__ ea,
                           float* __restrict__ agg)
{
    int idx = blockIdx.x * blockDim.x + threadIdx.x;
    if (idx >= EE * 32) return;
    int e = idx >> 5, c = idx & 31;
    int src = __ldg(&ei[e]);
    int dst = __ldg(&ei[EE + e]);
    float4 hv = __ldg((const float4*)h + (size_t)src * 32 + c);
    float4 ev = __ldg((const float4*)ea + (size_t)e * 32 + c);
    float m0 = fmaxf(hv.x + ev.x, 0.f);
    float m1 = fmaxf(hv.y + ev.y, 0.f);
    float m2 = fmaxf(hv.z + ev.z, 0.f);
    float m3 = fmaxf(hv.w + ev.w, 0.f);
    float* a = agg + (size_t)dst * 128 + c * 4;
    asm volatile("red.global.add.v4.f32 [%0], {%1, %2, %3, %4};"
                 :: "l"(a), "f"(m0), "f"(m1), "f"(m2), "f"(m3) : "memory");
}

// ============================================================================
// Heads: one warp per node. Output: u[3N] | s[N] | log_s[N] | disp[1] | safety[N]
// ============================================================================
__global__ void heads_kernel(const float* __restrict__ h,
                             const float* __restrict__ dw1, const float* __restrict__ db1,
                             const float* __restrict__ dw2, const float* __restrict__ db2,
                             const float* __restrict__ sw1, const float* __restrict__ sb1,
                             const float* __restrict__ sw2, const float* __restrict__ sb2,
                             const float* __restrict__ lds,
                             float* __restrict__ out, int rows)
{
    __shared__ float hs[8][128];
    const int warp = threadIdx.x >> 5, lane = threadIdx.x & 31;
    const int node = blockIdx.x * 8 + warp;
    float disp = 0.001f + log1pf(expf(*lds));
    if (blockIdx.x == 0 && threadIdx.x == 0) out[5 * NN] = disp;
    if (node >= rows) return;

    float4 hv = ((const float4*)h)[(size_t)node * 32 + lane];
    ((float4*)hs[warp])[lane] = hv;
    __syncwarp();

    float d0 = db1[lane], d1 = db1[lane + 32];
    float s0 = sb1[lane], s1 = sb1[lane + 32];
#pragma unroll 4
    for (int k = 0; k < 128; k++) {
        float xv = hs[warp][k];
        d0 = fmaf(xv, __ldg(&dw1[k * 64 + lane]),      d0);
        d1 = fmaf(xv, __ldg(&dw1[k * 64 + lane + 32]), d1);
        s0 = fmaf(xv, __ldg(&sw1[k * 64 + lane]),      s0);
        s1 = fmaf(xv, __ldg(&sw1[k * 64 + lane + 32]), s1);
    }
    d0 = fmaxf(d0, 0.f); d1 = fmaxf(d1, 0.f);
    s0 = fmaxf(s0, 0.f); s1 = fmaxf(s1, 0.f);

    float p0 = d0 * dw2[lane * 3 + 0] + d1 * dw2[(lane + 32) * 3 + 0];
    float p1 = d0 * dw2[lane * 3 + 1] + d1 * dw2[(lane + 32) * 3 + 1];
    float p2 = d0 * dw2[lane * 3 + 2] + d1 * dw2[(lane + 32) * 3 + 2];
    float ps = s0 * sw2[lane] + s1 * sw2[lane + 32];
    p0 = wsum(p0); p1 = wsum(p1); p2 = wsum(p2); ps = wsum(ps);

    if (lane == 0) {
        float ls = ps + sb2[0];
        ls = fminf(fmaxf(ls, 0.f), 30.f);
        float s = expf(ls);
        out[node * 3 + 0] = (p0 + db2[0]) * disp;
        out[node * 3 + 1] = (p1 + db2[1]) * disp;
        out[node * 3 + 2] = (p2 + db2[2]) * disp;
        out[3 * NN + node] = s;
        out[4 * NN + node] = ls;
        out[5 * NN + 1 + node] = 2.5e8f / (s + 1e-8f);
    }
}

// ============================================================================
extern "C" void kernel_launch(void* const* d_in, const int* in_sizes, int n_in,
                              void* d_out, int out_size)
{
    const float* x     = (const float*)d_in[0];
    const float* eattr = (const float*)d_in[1];
    const int*   ei    = (const int*)  d_in[2];
    const float* ne_w1 = (const float*)d_in[3];
    const float* ne_b1 = (const float*)d_in[4];
    const float* ne_w2 = (const float*)d_in[5];
    const float* ne_b2 = (const float*)d_in[6];
    const float* ne_g  = (const float*)d_in[7];
    const float* ne_be = (const float*)d_in[8];
    const float* ee_w1 = (const float*)d_in[9];
    const float* ee_b1 = (const float*)d_in[10];
    const float* ee_w2 = (const float*)d_in[11];
    const float* ee_b2 = (const float*)d_in[12];
    const float* ee_g  = (const float*)d_in[13];
    const float* ee_be = (const float*)d_in[14];
    const float* cw1   = (const float*)d_in[15];
    const float* cb1   = (const float*)d_in[16];
    const float* cw2   = (const float*)d_in[17];
    const float* cb2   = (const float*)d_in[18];
    const float* pn_g  = (const float*)d_in[19];
    const float* pn_be = (const float*)d_in[20];
    const float* dw1   = (const float*)d_in[21];
    const float* db1   = (const float*)d_in[22];
    const float* dw2   = (const float*)d_in[23];
    const float* db2   = (const float*)d_in[24];
    const float* sw1   = (const float*)d_in[25];
    const float* sb1   = (const float*)d_in[26];
    const float* sw2   = (const float*)d_in[27];
    const float* sb2   = (const float*)d_in[28];
    const float* ldsc  = (const float*)d_in[29];
    float* out = (float*)d_out;

    void *ph, *pa, *pt, *pe;
    cudaGetSymbolAddress(&ph, g_h);
    cudaGetSymbolAddress(&pa, g_agg);
    cudaGetSymbolAddress(&pt, g_t);
    cudaGetSymbolAddress(&pe, g_ea);
    float* hbuf = (float*)ph;
    float* abuf = (float*)pa;
    float* tbuf = (float*)pt;
    float* ebuf = (float*)pe;

    const int gsm = SMEM_WORDS * 4;   // 139264 bytes
    cudaFuncSetAttribute(gemm128_kernel<5, 0>, cudaFuncAttributeMaxDynamicSharedMemorySize, gsm);
    cudaFuncSetAttribute(gemm128_kernel<6, 0>, cudaFuncAttributeMaxDynamicSharedMemorySize, gsm);
    cudaFuncSetAttribute(gemm128_kernel<0, 1>, cudaFuncAttributeMaxDynamicSharedMemorySize, gsm);
    cudaFuncSetAttribute(gemm128_kernel<0, 2>, cudaFuncAttributeMaxDynamicSharedMemorySize, gsm);

    // node encoder: h = LN(mlp2(x)), agg = h
    gemm128_kernel<5, 0><<<148, 512, gsm>>>(x, NN, ne_w2, ne_b2, ne_w1, ne_b1,
                                            ne_g, ne_be, nullptr, hbuf, abuf);
    // edge encoder: ea = LN(mlp2(edge_attr))
    gemm128_kernel<6, 0><<<148, 512, gsm>>>(eattr, EE, ee_w2, ee_b2, ee_w1, ee_b1,
                                            ee_g, ee_be, nullptr, ebuf, nullptr);
    for (int l = 0; l < 3; l++) {
        msg_kernel<<<(EE * 32 + 255) / 256, 256>>>(ei, hbuf, ebuf, abuf);
        // t = relu(agg @ w1 + b1)
        gemm128_kernel<0, 1><<<148, 512, gsm>>>(abuf, NN, cw1 + (size_t)l * 16384, cb1 + l * 128,
                                                nullptr, nullptr, nullptr, nullptr, nullptr,
                                                tbuf, nullptr);
        // h = LN(h + relu(t @ w2 + b2)); agg = h
        gemm128_kernel<0, 2><<<148, 512, gsm>>>(tbuf, NN, cw2 + (size_t)l * 16384, cb2 + l * 128,
                                                nullptr, nullptr, pn_g + l * 128, pn_be + l * 128,
                                                hbuf, hbuf, abuf);
    }
    heads_kernel<<<(NN + 7) / 8, 256>>>(hbuf, dw1, db1, dw2, db2,
                                        sw1, sb1, sw2, sb2, ldsc, out, NN);
}

// round 5
// speedup vs baseline: 1.2708x; 1.0197x over previous
#include <cuda_runtime.h>
#include <cstdint>

#define NN 50000
#define EE 600000

// ---------------- scratch ---------------------------------------------------
__device__ float g_h  [(size_t)NN * 128];
__device__ float g_agg[(size_t)NN * 128];
__device__ float g_t  [(size_t)NN * 128];
__device__ float g_ea [(size_t)EE * 128];
// CSR scratch
__device__ int g_deg   [NN];
__device__ int g_start [NN + 1];
__device__ int g_cursor[NN];
__device__ int g_eidx  [EE];
__device__ int g_esrc  [EE];

// ---------------- helpers ----------------------------------------------------
// split (x0,x1) into packed bf16x2 hi and lo words: x ~= hi + lo, err ~2^-17
__device__ __forceinline__ void split2(float x0, float x1, uint32_t& hi, uint32_t& lo) {
    asm("cvt.rn.bf16x2.f32 %0, %2, %1;" : "=r"(hi) : "f"(x0), "f"(x1));
    float h0 = __uint_as_float(hi << 16);
    float h1 = __uint_as_float(hi & 0xffff0000u);
    float l0 = x0 - h0, l1 = x1 - h1;
    asm("cvt.rn.bf16x2.f32 %0, %2, %1;" : "=r"(lo) : "f"(l0), "f"(l1));
}
__device__ __forceinline__ void mma_bf16(float* d,
                                         uint32_t a0, uint32_t a1, uint32_t a2, uint32_t a3,
                                         uint32_t b0, uint32_t b1) {
    asm volatile("mma.sync.aligned.m16n8k16.row.col.f32.bf16.bf16.f32 "
        "{%0,%1,%2,%3}, {%4,%5,%6,%7}, {%8,%9}, {%0,%1,%2,%3};"
        : "+f"(d[0]), "+f"(d[1]), "+f"(d[2]), "+f"(d[3])
        : "r"(a0), "r"(a1), "r"(a2), "r"(a3), "r"(b0), "r"(b1));
}
__device__ __forceinline__ float wsum(float v) {
#pragma unroll
    for (int o = 16; o > 0; o >>= 1) v += __shfl_xor_sync(0xffffffffu, v, o);
    return v;
}

// SMEM word strides
#define KS2 68     // packed-k2 row stride
#define SD  132    // D epilogue stride

// word offsets inside dynamic smem (uint32 units); tile M = 64
#define OFF_AHI 0
#define OFF_ALO (64 * KS2)
#define OFF_BHI (2 * 64 * KS2)
#define OFF_BLO (2 * 64 * KS2 + 128 * KS2)
#define SMEM_WORDS (2 * 64 * KS2 + 2 * 128 * KS2)   // 26112 words = 104448 B

// ============================================================================
// Fused GEMM (out = f(A[rows,128] @ W[128,128])) via mma.sync bf16-split.
// Persistent CTAs; 64x128 tile per CTA; 8 warps; warp tile 32x32; 2 CTAs/SM.
// MODE 0: A = relu(x[KIN] @ w1 + b1) computed SIMT; epi: LN(D + b) -> out1
// MODE 1: A from gmem;                              epi: relu(D + b) -> out1
// MODE 2: A from gmem;                              epi: LN(hres + relu(D + b)) -> out1
// ============================================================================
template <int KIN, int MODE>
__global__ __launch_bounds__(256, 2)
void gemm128_kernel(const float* __restrict__ A, int rows,
                    const float* __restrict__ W, const float* __restrict__ bias,
                    const float* __restrict__ w1, const float* __restrict__ b1,
                    const float* __restrict__ gam, const float* __restrict__ bet,
                    const float* __restrict__ hres,
                    float* __restrict__ out1)
{
    extern __shared__ uint32_t dyn[];
    uint32_t* Ahi = dyn + OFF_AHI;
    uint32_t* Alo = dyn + OFF_ALO;
    uint32_t* Bhi = dyn + OFF_BHI;
    uint32_t* Blo = dyn + OFF_BLO;
    float*    Ds  = (float*)dyn;      // reused after mainloop: [64][SD]
    __shared__ float w1s[KIN > 0 ? KIN * 128 : 1];
    __shared__ float b1s[128], bs[128], gs[128], bes[128];

    const int tid  = threadIdx.x;
    const int lane = tid & 31;
    const int wrp  = tid >> 5;
    const int wm   = (wrp & 1) * 32;   // warp row offset (tile M=64)
    const int wn   = (wrp >> 1) * 32;  // warp col offset (4 groups)
    const int g    = lane >> 2;
    const int t4   = lane & 3;

    // ---- stage B = W (K-major) as packed bf16x2 hi/lo: Bs[n][k2] ----------
#pragma unroll
    for (int q = 0; q < 32; q++) {
        int i  = q * 256 + tid;
        int n  = i & 127, k2 = i >> 7;
        float v0 = W[(2 * k2) * 128 + n];
        float v1 = W[(2 * k2 + 1) * 128 + n];
        uint32_t h, l; split2(v0, v1, h, l);
        Bhi[n * KS2 + k2] = h;
        Blo[n * KS2 + k2] = l;
    }
    if (KIN > 0) {
        for (int i = tid; i < KIN * 128; i += 256) w1s[i] = w1[i];
        if (tid < 128) b1s[tid] = b1[tid];
    }
    if (tid < 128) {
        bs[tid] = bias[tid];
        if (MODE != 1) { gs[tid] = gam[tid]; bes[tid] = bet[tid]; }
    }
    __syncthreads();

    const int ntiles = (rows + 63) >> 6;
    for (int t = blockIdx.x; t < ntiles; t += gridDim.x) {
        const int row0 = t << 6;

        // ---------------- stage A tile (packed bf16x2 hi/lo) ----------------
        if (KIN > 0) {
            // layer-1 SIMT: row = tid>>2 (0..63), piece p = tid&3 -> 32 cols
            const int r = tid >> 2, p = tid & 3, rw = row0 + r;
            float xr[KIN > 0 ? KIN : 1];
#pragma unroll
            for (int j = 0; j < KIN; j++)
                xr[j] = (rw < rows) ? A[(size_t)rw * KIN + j] : 0.f;
#pragma unroll
            for (int j = 0; j < 16; j++) {
                int c = p * 32 + 2 * j;
                float a0 = b1s[c], a1 = b1s[c + 1];
#pragma unroll
                for (int k = 0; k < KIN; k++) {
                    a0 = fmaf(xr[k], w1s[k * 128 + c], a0);
                    a1 = fmaf(xr[k], w1s[k * 128 + c + 1], a1);
                }
                a0 = fmaxf(a0, 0.f); a1 = fmaxf(a1, 0.f);
                uint32_t h, l; split2(a0, a1, h, l);
                Ahi[r * KS2 + p * 16 + j] = h;
                Alo[r * KS2 + p * 16 + j] = l;
            }
        } else {
#pragma unroll
            for (int q = 0; q < 16; q++) {
                int i  = q * 256 + tid;
                int r  = i >> 6, k2 = i & 63;
                float2 v = (row0 + r < rows)
                    ? *(const float2*)(A + (size_t)(row0 + r) * 128 + 2 * k2)
                    : make_float2(0.f, 0.f);
                uint32_t h, l; split2(v.x, v.y, h, l);
                Ahi[r * KS2 + k2] = h;
                Alo[r * KS2 + k2] = l;
            }
        }
        __syncthreads();

        // ---------------- mainloop: 8 k-steps (k=16 each), 3 bf16 terms ----
        float d[2][4][4];
#pragma unroll
        for (int mt = 0; mt < 2; mt++)
#pragma unroll
            for (int nt = 0; nt < 4; nt++)
#pragma unroll
                for (int i = 0; i < 4; i++) d[mt][nt][i] = 0.f;

#pragma unroll 1
        for (int ks = 0; ks < 8; ks++) {
            const int kb = ks * 8 + t4;
            uint32_t ah[2][4], al[2][4];
#pragma unroll
            for (int mt = 0; mt < 2; mt++) {
                const int rb = (wm + mt * 16 + g) * KS2 + kb;
                ah[mt][0] = Ahi[rb];
                ah[mt][1] = Ahi[rb + 8 * KS2];
                ah[mt][2] = Ahi[rb + 4];
                ah[mt][3] = Ahi[rb + 8 * KS2 + 4];
                al[mt][0] = Alo[rb];
                al[mt][1] = Alo[rb + 8 * KS2];
                al[mt][2] = Alo[rb + 4];
                al[mt][3] = Alo[rb + 8 * KS2 + 4];
            }
#pragma unroll
            for (int nt = 0; nt < 4; nt++) {
                const int nb = (wn + nt * 8 + g) * KS2 + kb;
                uint32_t bh0 = Bhi[nb], bh1 = Bhi[nb + 4];
                uint32_t bl0 = Blo[nb], bl1 = Blo[nb + 4];
#pragma unroll
                for (int mt = 0; mt < 2; mt++) {
                    mma_bf16(d[mt][nt], ah[mt][0], ah[mt][1], ah[mt][2], ah[mt][3], bh0, bh1);
                    mma_bf16(d[mt][nt], al[mt][0], al[mt][1], al[mt][2], al[mt][3], bh0, bh1);
                    mma_bf16(d[mt][nt], ah[mt][0], ah[mt][1], ah[mt][2], ah[mt][3], bl0, bl1);
                }
            }
        }
        __syncthreads();   // done reading A region; reuse as D

        // ---------------- write D fragments into smem ----------------
#pragma unroll
        for (int mt = 0; mt < 2; mt++) {
            const int rb = wm + mt * 16 + g;
#pragma unroll
            for (int nt = 0; nt < 4; nt++) {
                const int cb = wn + nt * 8 + 2 * t4;
                *(float2*)(Ds + rb * SD + cb)       = make_float2(d[mt][nt][0], d[mt][nt][1]);
                *(float2*)(Ds + (rb + 8) * SD + cb) = make_float2(d[mt][nt][2], d[mt][nt][3]);
            }
        }
        __syncthreads();

        // ---------------- epilogue: row per thread (tid < 64) ----------------
        if (tid < 64) {
            const int rw = row0 + tid;
            const bool valid = rw < rows;
            if (MODE == 1) {
                if (valid) {
#pragma unroll
                    for (int q = 0; q < 32; q++) {
                        float4 v = *(const float4*)(Ds + tid * SD + q * 4);
                        float4 o;
                        o.x = fmaxf(v.x + bs[q * 4 + 0], 0.f);
                        o.y = fmaxf(v.y + bs[q * 4 + 1], 0.f);
                        o.z = fmaxf(v.z + bs[q * 4 + 2], 0.f);
                        o.w = fmaxf(v.w + bs[q * 4 + 3], 0.f);
                        ((float4*)(out1 + (size_t)rw * 128))[q] = o;
                    }
                }
            } else {
                float dv[128];
#pragma unroll
                for (int q = 0; q < 32; q++) {
                    float4 v = *(const float4*)(Ds + tid * SD + q * 4);
                    if (MODE == 2) {
                        float4 hv = valid ? ((const float4*)(hres + (size_t)rw * 128))[q]
                                          : make_float4(0.f, 0.f, 0.f, 0.f);
                        dv[q * 4 + 0] = hv.x + fmaxf(v.x + bs[q * 4 + 0], 0.f);
                        dv[q * 4 + 1] = hv.y + fmaxf(v.y + bs[q * 4 + 1], 0.f);
                        dv[q * 4 + 2] = hv.z + fmaxf(v.z + bs[q * 4 + 2], 0.f);
                        dv[q * 4 + 3] = hv.w + fmaxf(v.w + bs[q * 4 + 3], 0.f);
                    } else {
                        dv[q * 4 + 0] = v.x + bs[q * 4 + 0];
                        dv[q * 4 + 1] = v.y + bs[q * 4 + 1];
                        dv[q * 4 + 2] = v.z + bs[q * 4 + 2];
                        dv[q * 4 + 3] = v.w + bs[q * 4 + 3];
                    }
                }
                float sum = 0.f;
#pragma unroll
                for (int i = 0; i < 128; i++) sum += dv[i];
                float mean = sum * 0.0078125f;
                float var = 0.f;
#pragma unroll
                for (int i = 0; i < 128; i++) { float e = dv[i] - mean; var += e * e; }
                float inv = rsqrtf(var * 0.0078125f + 1e-5f);
                if (valid) {
#pragma unroll
                    for (int q = 0; q < 32; q++) {
                        float4 o;
                        o.x = (dv[q * 4 + 0] - mean) * inv * gs[q * 4 + 0] + bes[q * 4 + 0];
                        o.y = (dv[q * 4 + 1] - mean) * inv * gs[q * 4 + 1] + bes[q * 4 + 1];
                        o.z = (dv[q * 4 + 2] - mean) * inv * gs[q * 4 + 2] + bes[q * 4 + 2];
                        o.w = (dv[q * 4 + 3] - mean) * inv * gs[q * 4 + 3] + bes[q * 4 + 3];
                        ((float4*)(out1 + (size_t)rw * 128))[q] = o;
                    }
                }
            }
        }
        __syncthreads();  // smem reused next tile
    }
}

// ============================================================================
// CSR build: zero -> histogram -> scan -> scatter
// ============================================================================
__global__ void zero_kernel(int* __restrict__ deg) {
    int i = blockIdx.x * blockDim.x + threadIdx.x;
    if (i < NN) deg[i] = 0;
}
__global__ void hist_kernel(const int* __restrict__ ei, int* __restrict__ deg) {
    int e = blockIdx.x * blockDim.x + threadIdx.x;
    if (e < EE) atomicAdd(&deg[ei[EE + e]], 1);
}
__global__ __launch_bounds__(1024, 1)
void scan_kernel(const int* __restrict__ deg, int* __restrict__ start,
                 int* __restrict__ cursor) {
    __shared__ int sums[1024];
    const int t = threadIdx.x;
    const int CH = (NN + 1023) / 1024;
    const int lo = t * CH;
    const int hi = (lo + CH < NN) ? lo + CH : NN;
    int s = 0;
    for (int i = lo; i < hi; i++) s += deg[i];
    sums[t] = s;
    __syncthreads();
    for (int o = 1; o < 1024; o <<= 1) {
        int u = (t >= o) ? sums[t - o] : 0;
        __syncthreads();
        sums[t] += u;
        __syncthreads();
    }
    int running = sums[t] - s;   // exclusive offset of this chunk
    for (int i = lo; i < hi; i++) {
        start[i]  = running;
        cursor[i] = running;
        running += deg[i];
    }
    if (t == 1023) start[NN] = sums[1023];
}
__global__ void scatter_kernel(const int* __restrict__ ei, int* __restrict__ cursor,
                               int* __restrict__ eidx, int* __restrict__ esrc) {
    int e = blockIdx.x * blockDim.x + threadIdx.x;
    if (e >= EE) return;
    int dst = ei[EE + e];
    int pos = atomicAdd(&cursor[dst], 1);
    eidx[pos] = e;
    esrc[pos] = ei[e];
}

// ============================================================================
// Aggregation (gather): agg[n] = h[n] + sum_{e: dst=n} relu(h[src_e] + ea[e])
// warp per node, lane c handles float4 chunk c.
// ============================================================================
__global__ __launch_bounds__(256, 8)
void gather_kernel(const int* __restrict__ start,
                   const int* __restrict__ eidx, const int* __restrict__ esrc,
                   const float* __restrict__ h, const float* __restrict__ ea,
                   float* __restrict__ agg)
{
    const int warp = threadIdx.x >> 5, lane = threadIdx.x & 31;
    const int node = blockIdx.x * 8 + warp;
    if (node >= NN) return;
    const int s = __ldg(&start[node]);
    const int e = __ldg(&start[node + 1]);

    float4 acc = __ldg((const float4*)h + (size_t)node * 32 + lane);
    int j = s;
    for (; j + 1 < e; j += 2) {
        int e0 = __ldg(&eidx[j]),     e1 = __ldg(&eidx[j + 1]);
        int s0 = __ldg(&esrc[j]),     s1 = __ldg(&esrc[j + 1]);
        float4 ev0 = __ldg((const float4*)ea + (size_t)e0 * 32 + lane);
        float4 hv0 = __ldg((const float4*)h  + (size_t)s0 * 32 + lane);
        float4 ev1 = __ldg((const float4*)ea + (size_t)e1 * 32 + lane);
        float4 hv1 = __ldg((const float4*)h  + (size_t)s1 * 32 + lane);
        acc.x += fmaxf(hv0.x + ev0.x, 0.f) + fmaxf(hv1.x + ev1.x, 0.f);
        acc.y += fmaxf(hv0.y + ev0.y, 0.f) + fmaxf(hv1.y + ev1.y, 0.f);
        acc.z += fmaxf(hv0.z + ev0.z, 0.f) + fmaxf(hv1.z + ev1.z, 0.f);
        acc.w += fmaxf(hv0.w + ev0.w, 0.f) + fmaxf(hv1.w + ev1.w, 0.f);
    }
    if (j < e) {
        int e0 = __ldg(&eidx[j]);
        int s0 = __ldg(&esrc[j]);
        float4 ev0 = __ldg((const float4*)ea + (size_t)e0 * 32 + lane);
        float4 hv0 = __ldg((const float4*)h  + (size_t)s0 * 32 + lane);
        acc.x += fmaxf(hv0.x + ev0.x, 0.f);
        acc.y += fmaxf(hv0.y + ev0.y, 0.f);
        acc.z += fmaxf(hv0.z + ev0.z, 0.f);
        acc.w += fmaxf(hv0.w + ev0.w, 0.f);
    }
    ((float4*)agg)[(size_t)node * 32 + lane] = acc;
}

// ============================================================================
// Heads: one warp per node. Output: u[3N] | s[N] | log_s[N] | disp[1] | safety[N]
// ============================================================================
__global__ void heads_kernel(const float* __restrict__ h,
                             const float* __restrict__ dw1, const float* __restrict__ db1,
                             const float* __restrict__ dw2, const float* __restrict__ db2,
                             const float* __restrict__ sw1, const float* __restrict__ sb1,
                             const float* __restrict__ sw2, const float* __restrict__ sb2,
                             const float* __restrict__ lds,
                             float* __restrict__ out, int rows)
{
    __shared__ float hs[8][128];
    const int warp = threadIdx.x >> 5, lane = threadIdx.x & 31;
    const int node = blockIdx.x * 8 + warp;
    float disp = 0.001f + log1pf(expf(*lds));
    if (blockIdx.x == 0 && threadIdx.x == 0) out[5 * NN] = disp;
    if (node >= rows) return;

    float4 hv = ((const float4*)h)[(size_t)node * 32 + lane];
    ((float4*)hs[warp])[lane] = hv;
    __syncwarp();

    float d0 = db1[lane], d1 = db1[lane + 32];
    float s0 = sb1[lane], s1 = sb1[lane + 32];
#pragma unroll 4
    for (int k = 0; k < 128; k++) {
        float xv = hs[warp][k];
        d0 = fmaf(xv, __ldg(&dw1[k * 64 + lane]),      d0);
        d1 = fmaf(xv, __ldg(&dw1[k * 64 + lane + 32]), d1);
        s0 = fmaf(xv, __ldg(&sw1[k * 64 + lane]),      s0);
        s1 = fmaf(xv, __ldg(&sw1[k * 64 + lane + 32]), s1);
    }
    d0 = fmaxf(d0, 0.f); d1 = fmaxf(d1, 0.f);
    s0 = fmaxf(s0, 0.f); s1 = fmaxf(s1, 0.f);

    float p0 = d0 * dw2[lane * 3 + 0] + d1 * dw2[(lane + 32) * 3 + 0];
    float p1 = d0 * dw2[lane * 3 + 1] + d1 * dw2[(lane + 32) * 3 + 1];
    float p2 = d0 * dw2[lane * 3 + 2] + d1 * dw2[(lane + 32) * 3 + 2];
    float ps = s0 * sw2[lane] + s1 * sw2[lane + 32];
    p0 = wsum(p0); p1 = wsum(p1); p2 = wsum(p2); ps = wsum(ps);

    if (lane == 0) {
        float ls = ps + sb2[0];
        ls = fminf(fmaxf(ls, 0.f), 30.f);
        float s = expf(ls);
        out[node * 3 + 0] = (p0 + db2[0]) * disp;
        out[node * 3 + 1] = (p1 + db2[1]) * disp;
        out[node * 3 + 2] = (p2 + db2[2]) * disp;
        out[3 * NN + node] = s;
        out[4 * NN + node] = ls;
        out[5 * NN + 1 + node] = 2.5e8f / (s + 1e-8f);
    }
}

// ============================================================================
extern "C" void kernel_launch(void* const* d_in, const int* in_sizes, int n_in,
                              void* d_out, int out_size)
{
    const float* x     = (const float*)d_in[0];
    const float* eattr = (const float*)d_in[1];
    const int*   ei    = (const int*)  d_in[2];
    const float* ne_w1 = (const float*)d_in[3];
    const float* ne_b1 = (const float*)d_in[4];
    const float* ne_w2 = (const float*)d_in[5];
    const float* ne_b2 = (const float*)d_in[6];
    const float* ne_g  = (const float*)d_in[7];
    const float* ne_be = (const float*)d_in[8];
    const float* ee_w1 = (const float*)d_in[9];
    const float* ee_b1 = (const float*)d_in[10];
    const float* ee_w2 = (const float*)d_in[11];
    const float* ee_b2 = (const float*)d_in[12];
    const float* ee_g  = (const float*)d_in[13];
    const float* ee_be = (const float*)d_in[14];
    const float* cw1   = (const float*)d_in[15];
    const float* cb1   = (const float*)d_in[16];
    const float* cw2   = (const float*)d_in[17];
    const float* cb2   = (const float*)d_in[18];
    const float* pn_g  = (const float*)d_in[19];
    const float* pn_be = (const float*)d_in[20];
    const float* dw1   = (const float*)d_in[21];
    const float* db1   = (const float*)d_in[22];
    const float* dw2   = (const float*)d_in[23];
    const float* db2   = (const float*)d_in[24];
    const float* sw1   = (const float*)d_in[25];
    const float* sb1   = (const float*)d_in[26];
    const float* sw2   = (const float*)d_in[27];
    const float* sb2   = (const float*)d_in[28];
    const float* ldsc  = (const float*)d_in[29];
    float* out = (float*)d_out;

    void *ph, *pa, *pt, *pe, *pd, *ps, *pc, *px, *py;
    cudaGetSymbolAddress(&ph, g_h);
    cudaGetSymbolAddress(&pa, g_agg);
    cudaGetSymbolAddress(&pt, g_t);
    cudaGetSymbolAddress(&pe, g_ea);
    cudaGetSymbolAddress(&pd, g_deg);
    cudaGetSymbolAddress(&ps, g_start);
    cudaGetSymbolAddress(&pc, g_cursor);
    cudaGetSymbolAddress(&px, g_eidx);
    cudaGetSymbolAddress(&py, g_esrc);
    float* hbuf = (float*)ph;
    float* abuf = (float*)pa;
    float* tbuf = (float*)pt;
    float* ebuf = (float*)pe;
    int* deg    = (int*)pd;
    int* startb = (int*)ps;
    int* cursor = (int*)pc;
    int* eidx   = (int*)px;
    int* esrc   = (int*)py;

    const int gsm = SMEM_WORDS * 4;   // 104448 bytes
    cudaFuncSetAttribute(gemm128_kernel<5, 0>, cudaFuncAttributeMaxDynamicSharedMemorySize, gsm);
    cudaFuncSetAttribute(gemm128_kernel<6, 0>, cudaFuncAttributeMaxDynamicSharedMemorySize, gsm);
    cudaFuncSetAttribute(gemm128_kernel<0, 1>, cudaFuncAttributeMaxDynamicSharedMemorySize, gsm);
    cudaFuncSetAttribute(gemm128_kernel<0, 2>, cudaFuncAttributeMaxDynamicSharedMemorySize, gsm);

    // ---- CSR build (once per launch) ----
    zero_kernel<<<(NN + 255) / 256, 256>>>(deg);
    hist_kernel<<<(EE + 255) / 256, 256>>>(ei, deg);
    scan_kernel<<<1, 1024>>>(deg, startb, cursor);
    scatter_kernel<<<(EE + 255) / 256, 256>>>(ei, cursor, eidx, esrc);

    // node encoder: h = LN(mlp2(x))
    gemm128_kernel<5, 0><<<296, 256, gsm>>>(x, NN, ne_w2, ne_b2, ne_w1, ne_b1,
                                            ne_g, ne_be, nullptr, hbuf);
    // edge encoder: ea = LN(mlp2(edge_attr))
    gemm128_kernel<6, 0><<<296, 256, gsm>>>(eattr, EE, ee_w2, ee_b2, ee_w1, ee_b1,
                                            ee_g, ee_be, nullptr, ebuf);
    for (int l = 0; l < 3; l++) {
        gather_kernel<<<(NN + 7) / 8, 256>>>(startb, eidx, esrc, hbuf, ebuf, abuf);
        // t = relu(agg @ w1 + b1)
        gemm128_kernel<0, 1><<<296, 256, gsm>>>(abuf, NN, cw1 + (size_t)l * 16384, cb1 + l * 128,
                                                nullptr, nullptr, nullptr, nullptr, nullptr, tbuf);
        // h = LN(h + relu(t @ w2 + b2))
        gemm128_kernel<0, 2><<<296, 256, gsm>>>(tbuf, NN, cw2 + (size_t)l * 16384, cb2 + l * 128,
                                                nullptr, nullptr, pn_g + l * 128, pn_be + l * 128,
                                                hbuf, hbuf);
    }
    heads_kernel<<<(NN + 7) / 8, 256>>>(hbuf, dw1, db1, dw2, db2,
                                        sw1, sb1, sw2, sb2, ldsc, out, NN);
}